// round 6
// baseline (speedup 1.0000x reference)
#include <cuda_runtime.h>
#include <math.h>

typedef unsigned long long ull;

// Problem dims (fixed by setup_inputs)
#define BATCH 256
#define DM    512
#define NN    1024
#define KTOT  (2*NN)

// Phase-1 tiling
#define BT 32
#define NT 32
#define DC 64
#define ZSPLIT 8
#define DPER (DM / ZSPLIT)       // 64 == DC
#define P1_THREADS 256

// Phase-2 tiling (split-K SGEMM)
#define BM 64
#define BN 64
#define BK 16
#define SPLITK 16
#define KCHUNK (KTOT / SPLITK)   // 128

// Scratch (static device globals — no allocation allowed)
__device__ float g_sumsP[ZSPLIT][BATCH * KTOT];
__device__ float g_sums[BATCH * KTOT];
__device__ float g_part[SPLITK * BATCH * DM];

// ---------------------------------------------------------------------------
// Packed f32x2 helpers (Blackwell)
// ---------------------------------------------------------------------------
__device__ __forceinline__ ull pack2(float lo, float hi) {
    ull r; asm("mov.b64 %0, {%1, %2};" : "=l"(r) : "f"(lo), "f"(hi)); return r;
}
__device__ __forceinline__ void unpack2(ull v, float& lo, float& hi) {
    asm("mov.b64 {%0, %1}, %2;" : "=f"(lo), "=f"(hi) : "l"(v));
}
__device__ __forceinline__ void fma2(ull& d, ull a, ull b) {
    asm("fma.rn.f32x2 %0, %1, %2, %3;" : "=l"(d) : "l"(a), "l"(b), "l"(d));
}
__device__ __forceinline__ ull fma2v(ull a, ull b, ull c) {
    ull d; asm("fma.rn.f32x2 %0, %1, %2, %3;" : "=l"(d) : "l"(a), "l"(b), "l"(c)); return d;
}
__device__ __forceinline__ ull add2v(ull a, ull b) {
    ull d; asm("add.rn.f32x2 %0, %1, %2;" : "=l"(d) : "l"(a), "l"(b)); return d;
}
__device__ __forceinline__ ull mul2v(ull a, ull b) {
    ull d; asm("mul.rn.f32x2 %0, %1, %2;" : "=l"(d) : "l"(a), "l"(b)); return d;
}

// ---------------------------------------------------------------------------
// Phase 1: resonance partial sums over one 64-wide d-slab.
// Grid: (32, 8, 8) = 2048 blocks x 256 threads. Per d (4 thetas):
// 2 via MUFU sincos, 2 via one packed-f32x2 polynomial (pi-based reduction,
// single sign fixup). Balances MUFU (32 cyc) against issue (~44 slots).
// ---------------------------------------------------------------------------
__global__ void __launch_bounds__(P1_THREADS) phase1_kernel(
    const float* __restrict__ xr, const float* __restrict__ xi,
    const float* __restrict__ W,  const float* __restrict__ Bm)
{
    __shared__ float xsT[DC][BT + 2];        // [d][b], stride 34 (8B-aligned pairs)
    __shared__ float wbT[DC][2 * NT + 4];    // [d][(w,b) pairs], stride 132 (16B quads)

    const int t  = threadIdx.x;
    const int tn = t & 15;
    const int tb = t >> 4;
    const int b0 = blockIdx.y * BT;
    const int n0 = blockIdx.x * NT;
    const int z  = blockIdx.z;
    const int d0 = z * DPER;

    // Stage 32 rows x 64 d into transposed smem (8 iters/thread).
    #pragma unroll
    for (int i = t; i < BT * DC; i += P1_THREADS) {
        const int r = i >> 6;
        const int c = i & (DC - 1);
        const int gx = (b0 + r) * DM + d0 + c;
        xsT[c][r] = xr[gx] + xi[gx];
        const int gw = (n0 + r) * DM + d0 + c;
        const float winv = __fdividef(1.0f, 1.0f + fabsf(W[gw]));
        *(float2*)&wbT[c][2 * r] = make_float2(winv, Bm[gw]);
    }
    __syncthreads();

    // Hoisted packed constants (identical hi/lo halves).
    const ull INVPI2  = pack2(0.3183098861837907f, 0.3183098861837907f);
    const ull MAGIC2  = pack2(12582912.0f, 12582912.0f);        // 1.5*2^23
    const ull NMAGIC2 = pack2(-12582912.0f, -12582912.0f);
    const ull NPIHI2  = pack2(-3.14159274101f, -3.14159274101f); // -(fp32 pi)
    const ull NPILO2  = pack2(8.7422776573e-8f, 8.7422776573e-8f);
    const ull S4_2 = pack2( 2.7557319e-6f,  2.7557319e-6f);
    const ull S3_2 = pack2(-1.9841270e-4f, -1.9841270e-4f);
    const ull S2_2 = pack2( 8.3333333e-3f,  8.3333333e-3f);
    const ull S1_2 = pack2(-1.6666667e-1f, -1.6666667e-1f);
    const ull C4_2 = pack2( 2.4801587e-5f,  2.4801587e-5f);
    const ull C3_2 = pack2(-1.3888889e-3f, -1.3888889e-3f);
    const ull C2_2 = pack2( 4.1666667e-2f,  4.1666667e-2f);
    const ull CH2  = pack2(-0.5f, -0.5f);
    const ull ONE2 = pack2(1.0f, 1.0f);

    float aS00 = 0.f, aS01 = 0.f, aS10 = 0.f, aS11 = 0.f;
    float aC00 = 0.f, aC01 = 0.f, aC10 = 0.f, aC11 = 0.f;

    #pragma unroll 8
    for (int d = 0; d < DC; d++) {
        const ull   x2 = *(const ull*)&xsT[d][2 * tb];         // (x0, x1) packed
        const float4 wb = *(const float4*)&wbT[d][4 * tn];     // (w0,b0,w1,b1)
        float xlo, xhi; unpack2(x2, xlo, xhi);

        // --- MUFU path: neuron 0 for both batches ---
        float s, c;
        __sincosf(fmaf(xlo, wb.x, wb.y), &s, &c); aS00 += s; aC00 += c;
        __sincosf(fmaf(xhi, wb.x, wb.y), &s, &c); aS10 += s; aC10 += c;

        // --- Packed poly path: neuron 1 for both batches ---
        const ull th2 = fma2v(x2, pack2(wb.z, wb.z), pack2(wb.w, wb.w));
        const ull m   = fma2v(th2, INVPI2, MAGIC2);            // round(th/pi)+magic
        float mlo, mhi; unpack2(m, mlo, mhi);
        const int q0 = __float_as_int(mlo);                    // low bits = n
        const int q1 = __float_as_int(mhi);
        const ull kf = add2v(m, NMAGIC2);                      // n as f32 pair
        ull r2 = fma2v(kf, NPIHI2, th2);                       // r = th - n*pi
        r2 = fma2v(kf, NPILO2, r2);
        const ull u2 = mul2v(r2, r2);
        ull sp = fma2v(S4_2, u2, S3_2);
        sp = fma2v(sp, u2, S2_2);
        sp = fma2v(sp, u2, S1_2);
        sp = fma2v(sp, mul2v(r2, u2), r2);                     // sin(r) pair
        ull cp = fma2v(C4_2, u2, C3_2);
        cp = fma2v(cp, u2, C2_2);
        cp = fma2v(cp, u2, CH2);
        cp = fma2v(cp, u2, ONE2);                              // cos(r) pair
        float s0, s1, c0, c1;
        unpack2(sp, s0, s1);
        unpack2(cp, c0, c1);
        const int g0 = q0 << 31, g1 = q1 << 31;                // (-1)^n sign
        aS01 += __int_as_float(__float_as_int(s0) ^ g0);
        aC01 += __int_as_float(__float_as_int(c0) ^ g0);
        aS11 += __int_as_float(__float_as_int(s1) ^ g1);
        aC11 += __int_as_float(__float_as_int(c1) ^ g1);
    }

    float* outp = g_sumsP[z];
    const int br0 = b0 + 2 * tb, br1 = br0 + 1;
    const int nc0 = n0 + 2 * tn;
    *(float2*)&outp[br0 * KTOT + nc0]      = make_float2(aC00, aC01);
    *(float2*)&outp[br1 * KTOT + nc0]      = make_float2(aC10, aC11);
    *(float2*)&outp[br0 * KTOT + NN + nc0] = make_float2(aS00, aS01);
    *(float2*)&outp[br1 * KTOT + NN + nc0] = make_float2(aS10, aS11);
}

// ---------------------------------------------------------------------------
// Combine the 8 d-slab partials. 2 threads per float4 output, shfl merge.
// ---------------------------------------------------------------------------
__global__ void __launch_bounds__(256) combine_kernel()
{
    const int t = threadIdx.x;
    const int zg = t & 1;
    const int o4 = blockIdx.x * 128 + (t >> 1);
    const int i  = o4 * 4;

    float4 v = make_float4(0.f, 0.f, 0.f, 0.f);
    #pragma unroll
    for (int j = 0; j < 4; j++) {
        const float4 p = *(const float4*)&g_sumsP[zg * 4 + j][i];
        v.x += p.x; v.y += p.y; v.z += p.z; v.w += p.w;
    }
    v.x += __shfl_xor_sync(0xFFFFFFFFu, v.x, 1);
    v.y += __shfl_xor_sync(0xFFFFFFFFu, v.y, 1);
    v.z += __shfl_xor_sync(0xFFFFFFFFu, v.z, 1);
    v.w += __shfl_xor_sync(0xFFFFFFFFu, v.w, 1);
    if (zg == 0) *(float4*)&g_sums[i] = v;
}

// ---------------------------------------------------------------------------
// Phase 2: split-K SGEMM with packed f32x2 FMA.
// Grid: (8, 4, 16) = 512 blocks x 256 threads.
// ---------------------------------------------------------------------------
__global__ void __launch_bounds__(256) phase2_kernel(
    const float* __restrict__ PC, const float* __restrict__ PS)
{
    __shared__ float As[BK][BM + 4];
    __shared__ float Bs[BK][BN + 4];

    const int t  = threadIdx.x;
    const int tx = t & 15;
    const int ty = t >> 4;
    const int m0 = blockIdx.x * BN;
    const int b0 = blockIdx.y * BM;
    const int z  = blockIdx.z;
    const int kbase = z * KCHUNK;

    const float* __restrict__ Wsel = (kbase < NN) ? PC : PS;
    const int koff = (kbase < NN) ? 0 : NN;

    ull acc2[4][2];
    #pragma unroll
    for (int i = 0; i < 4; i++) { acc2[i][0] = 0ull; acc2[i][1] = 0ull; }

    for (int k0 = kbase; k0 < kbase + KCHUNK; k0 += BK) {
        #pragma unroll
        for (int i = t; i < BM * BK; i += 256) {
            const int r  = i >> 4;
            const int kk = i & 15;
            As[kk][r] = g_sums[(b0 + r) * KTOT + k0 + kk];
        }
        #pragma unroll
        for (int i = t; i < BN * BK; i += 256) {
            const int r  = i >> 4;
            const int kk = i & 15;
            Bs[kk][r] = Wsel[(m0 + r) * NN + (k0 + kk - koff)];
        }
        __syncthreads();

        #pragma unroll
        for (int kk = 0; kk < BK; kk++) {
            const float4 av = *(const float4*)&As[kk][ty * 4];
            const float4 bv = *(const float4*)&Bs[kk][tx * 4];
            const ull b01 = pack2(bv.x, bv.y);
            const ull b23 = pack2(bv.z, bv.w);
            const float a[4] = {av.x, av.y, av.z, av.w};
            #pragma unroll
            for (int i = 0; i < 4; i++) {
                const ull ai = pack2(a[i], a[i]);
                fma2(acc2[i][0], ai, b01);
                fma2(acc2[i][1], ai, b23);
            }
        }
        __syncthreads();
    }

    float* outp = &g_part[z * BATCH * DM];
    #pragma unroll
    for (int i = 0; i < 4; i++) {
        float v0, v1, v2, v3;
        unpack2(acc2[i][0], v0, v1);
        unpack2(acc2[i][1], v2, v3);
        *(float4*)&outp[(b0 + ty * 4 + i) * DM + m0 + tx * 4] =
            make_float4(v0, v1, v2, v3);
    }
}

// ---------------------------------------------------------------------------
// Phase 3: reduce split-K partials + SiLU. 4 threads per float4 output.
// ---------------------------------------------------------------------------
__global__ void __launch_bounds__(256) phase3_kernel(float* __restrict__ out)
{
    const int t  = threadIdx.x;
    const int zg = t & 3;
    const int o4 = blockIdx.x * 64 + (t >> 2);
    const int i  = o4 * 4;

    float4 v = make_float4(0.f, 0.f, 0.f, 0.f);
    #pragma unroll
    for (int j = 0; j < 4; j++) {
        const float4 p = *(const float4*)&g_part[(zg * 4 + j) * BATCH * DM + i];
        v.x += p.x; v.y += p.y; v.z += p.z; v.w += p.w;
    }
    #pragma unroll
    for (int m = 1; m <= 2; m <<= 1) {
        v.x += __shfl_xor_sync(0xFFFFFFFFu, v.x, m);
        v.y += __shfl_xor_sync(0xFFFFFFFFu, v.y, m);
        v.z += __shfl_xor_sync(0xFFFFFFFFu, v.z, m);
        v.w += __shfl_xor_sync(0xFFFFFFFFu, v.w, m);
    }
    if (zg == 0) {
        float4 o;
        o.x = v.x / (1.0f + __expf(-v.x));
        o.y = v.y / (1.0f + __expf(-v.y));
        o.z = v.z / (1.0f + __expf(-v.z));
        o.w = v.w / (1.0f + __expf(-v.w));
        *(float4*)&out[i] = o;
    }
}

extern "C" void kernel_launch(void* const* d_in, const int* in_sizes, int n_in,
                              void* d_out, int out_size)
{
    (void)in_sizes; (void)n_in; (void)out_size;
    const float* xr = (const float*)d_in[0];
    const float* xi = (const float*)d_in[1];
    const float* W  = (const float*)d_in[2];
    const float* Bm = (const float*)d_in[3];
    const float* PC = (const float*)d_in[4];
    const float* PS = (const float*)d_in[5];
    float* out = (float*)d_out;

    dim3 g1(NN / NT, BATCH / BT, ZSPLIT);      // 2048 blocks
    phase1_kernel<<<g1, P1_THREADS>>>(xr, xi, W, Bm);

    combine_kernel<<<BATCH * KTOT / 4 / 128, 256>>>();          // 1024 blocks

    dim3 g2(DM / BN, BATCH / BM, SPLITK);      // 512 blocks
    phase2_kernel<<<g2, 256>>>(PC, PS);

    phase3_kernel<<<BATCH * DM / 4 / 64, 256>>>(out);           // 512 blocks
}